// round 1
// baseline (speedup 1.0000x reference)
#include <cuda_runtime.h>
#include <cstdint>

// Truncated path signature (Chen's identity), trunc=4, B=128, S=512, D=8.
// One CTA per batch element. 512 threads; thread t owns triple (i,j,k):
//   - s3[ijk] (1 reg), s4[ijk][0..7] (4 x f32x2 regs)
//   - private replicated copies of s1[i], s2[ij]  -> NO syncs in main loop.
// Increments precomputed into shared memory once.

#define BDIM 512
#define DSZ 8
#define SLEN 512
#define TSTEPS 511
#define OUT_PER_B (DSZ + DSZ*DSZ + DSZ*DSZ*DSZ + DSZ*DSZ*DSZ*DSZ)  // 4680

__global__ __launch_bounds__(BDIM, 1)
void sig_kernel(const float* __restrict__ path, float* __restrict__ out) {
    __shared__ float inc[TSTEPS * DSZ];   // 4088 floats = 16352 B

    const int b   = blockIdx.x;
    const int tid = threadIdx.x;
    const float* prow = path + (size_t)b * (SLEN * DSZ);

    // Precompute segment increments into shared (coalesced global reads).
    #pragma unroll
    for (int e = tid; e < TSTEPS * DSZ; e += BDIM)
        inc[e] = prow[e + DSZ] - prow[e];
    __syncthreads();

    const int i = tid >> 6;
    const int j = (tid >> 3) & 7;
    const int k = tid & 7;

    float s1 = 0.0f, s2 = 0.0f, s3 = 0.0f;
    unsigned long long s4p0 = 0ull, s4p1 = 0ull, s4p2 = 0ull, s4p3 = 0ull;

    const unsigned long long* __restrict__ incq =
        reinterpret_cast<const unsigned long long*>(inc);

    #pragma unroll 4
    for (int t = 0; t < TSTEPS; ++t) {
        const int base8 = t * DSZ;
        // dx pairs (LDS.64, broadcast) + 3 scalars (LDS.32, broadcast-ish)
        unsigned long long d01 = incq[t * 4 + 0];
        unsigned long long d23 = incq[t * 4 + 1];
        unsigned long long d45 = incq[t * 4 + 2];
        unsigned long long d67 = incq[t * 4 + 3];
        float dxi = inc[base8 + i];
        float dxj = inc[base8 + j];
        float dxk = inc[base8 + k];

        float p = dxj * dxk;
        float q = dxi * p;
        float u = dxk * s2;     // reads OLD s2
        float v = p   * s1;     // reads OLD s1

        // inner = s3 + u/2 + v/6 + q/24   (uses OLD s3)  -- FFMA-imm forms
        float inner = fmaf(0.5f, u, s3);
        inner = fmaf(0.16666666666666667f, v, inner);
        inner = fmaf(0.04166666666666667f, q, inner);

        // s4[l] += dx[l] * inner  as 4 packed f32x2 FMAs
        unsigned long long innp;
        {
            uint32_t ir = __float_as_uint(inner);
            asm("mov.b64 %0, {%1, %1};" : "=l"(innp) : "r"(ir));
        }
        asm("fma.rn.f32x2 %0, %1, %2, %0;" : "+l"(s4p0) : "l"(d01), "l"(innp));
        asm("fma.rn.f32x2 %0, %1, %2, %0;" : "+l"(s4p1) : "l"(d23), "l"(innp));
        asm("fma.rn.f32x2 %0, %1, %2, %0;" : "+l"(s4p2) : "l"(d45), "l"(innp));
        asm("fma.rn.f32x2 %0, %1, %2, %0;" : "+l"(s4p3) : "l"(d67), "l"(innp));

        // s3' = s3 + u + v/2 + q/6
        s3 = s3 + u;
        s3 = fmaf(0.5f, v, s3);
        s3 = fmaf(0.16666666666666667f, q, s3);

        // s2' = s2 + dxj*(s1_old + dxi/2)
        s2 = fmaf(dxj, fmaf(0.5f, dxi, s1), s2);
        // s1' = s1 + dxi
        s1 = s1 + dxi;
    }

    // ---- Epilogue: write [s1 | s2 | s3 | s4] for this batch ----
    float* ob = out + (size_t)b * OUT_PER_B;

    if ((tid & 63) == 0) ob[i] = s1;                 // unique owner per i (j=k=0)
    if ((tid & 7)  == 0) ob[DSZ + (tid >> 3)] = s2;  // unique owner per (i,j)
    ob[DSZ + DSZ*DSZ + tid] = s3;

    // s4: 4096 floats starting at offset 584; thread t writes [t*8, t*8+8)
    float* s4out = ob + (DSZ + DSZ*DSZ + DSZ*DSZ*DSZ) + tid * 8;
    ulonglong2* s4v = reinterpret_cast<ulonglong2*>(s4out);  // 16B-aligned
    s4v[0] = make_ulonglong2(s4p0, s4p1);
    s4v[1] = make_ulonglong2(s4p2, s4p3);
}

extern "C" void kernel_launch(void* const* d_in, const int* in_sizes, int n_in,
                              void* d_out, int out_size) {
    const float* path = (const float*)d_in[0];
    float* out = (float*)d_out;
    sig_kernel<<<128, BDIM>>>(path, out);
}

// round 2
// speedup vs baseline: 1.0978x; 1.0978x over previous
#include <cuda_runtime.h>
#include <cstdint>

// Truncated path signature (Chen), trunc=4, B=128, S=512, D=8.
// One CTA per batch, 256 threads; thread owns (i, j, k-pair m) -> 16 s4 elems.
// Entire scalar recurrence kept in duplicated-lane f32x2 registers so every
// packed FMA operand is layout-ready (zero MOV duplication in the loop).

#define BDIM 256
#define DSZ 8
#define SLEN 512
#define TSTEPS 511
#define OUT_PER_B 4680   // 8 + 64 + 512 + 4096

typedef unsigned long long u64;

__device__ __forceinline__ u64 pack2(float x) {
    u64 r; uint32_t xi = __float_as_uint(x);
    asm("mov.b64 %0, {%1, %1};" : "=l"(r) : "r"(xi));
    return r;
}
__device__ __forceinline__ u64 f2mul(u64 a, u64 b) {
    u64 r; asm("mul.rn.f32x2 %0, %1, %2;" : "=l"(r) : "l"(a), "l"(b)); return r;
}
__device__ __forceinline__ u64 f2fma(u64 a, u64 b, u64 c) {
    u64 r; asm("fma.rn.f32x2 %0, %1, %2, %3;" : "=l"(r) : "l"(a), "l"(b), "l"(c)); return r;
}
__device__ __forceinline__ u64 f2add(u64 a, u64 b) {
    u64 r; asm("add.rn.f32x2 %0, %1, %2;" : "=l"(r) : "l"(a), "l"(b)); return r;
}
__device__ __forceinline__ float lo32(u64 a) { return __uint_as_float((uint32_t)a); }

__global__ __launch_bounds__(BDIM, 1)
void sig_kernel(const float* __restrict__ path, float* __restrict__ out) {
    __shared__ __align__(16) float inc[TSTEPS * DSZ];   // plain increments (16352 B)
    __shared__ __align__(16) u64  dupv[TSTEPS * DSZ];   // (dx,dx) dup pairs (32704 B)

    const int b   = blockIdx.x;
    const int tid = threadIdx.x;
    const float* prow = path + (size_t)b * (SLEN * DSZ);

    for (int e = tid; e < TSTEPS * DSZ; e += BDIM) {
        float v = prow[e + DSZ] - prow[e];
        inc[e]  = v;
        dupv[e] = pack2(v);
    }
    __syncthreads();

    const int i = tid >> 5;          // 0..7
    const int j = (tid >> 2) & 7;    // 0..7
    const int m = tid & 3;           // k-pair: k = 2m, 2m+1

    // Duplicated-lane state
    u64 s1d = 0ull, s2d = 0ull, s3d0 = 0ull, s3d1 = 0ull;
    u64 s4a[8];                      // [0..3]: k=2m rows (l-pairs), [4..7]: k=2m+1
    #pragma unroll
    for (int z = 0; z < 8; z++) s4a[z] = 0ull;

    const u64 chalf = pack2(0.5f);
    const u64 c6    = pack2(0.16666666666666667f);
    const u64 c24   = pack2(0.041666666666666667f);

    #pragma unroll 4
    for (int t = 0; t < TSTEPS; ++t) {
        // l-direction plain pairs: (d0,d1),(d2,d3),(d4,d5),(d6,d7) via 2x LDS.128
        const ulonglong2* incq = reinterpret_cast<const ulonglong2*>(inc + t * DSZ);
        ulonglong2 A = incq[0];      // A.x=(d0,d1) A.y=(d2,d3)
        ulonglong2 Bq = incq[1];     // Bq.x=(d4,d5) Bq.y=(d6,d7)
        // this thread's two k dup-pairs: adjacent -> one LDS.128
        ulonglong2 KD = *reinterpret_cast<const ulonglong2*>(dupv + t * DSZ + 2 * m);
        u64 did = dupv[t * DSZ + i];
        u64 djd = dupv[t * DSZ + j];

        // scalar chain, fully packed-duplicated (reads OLD s1,s2,s3)
        u64 bd = f2mul(did, djd);                 // dxi*dxj
        u64 gd = f2mul(djd, s1d);                 // dxj*s1
        u64 ap = f2fma(chalf, s2d, f2fma(c6, gd, f2mul(c24, bd)));  // alpha
        u64 gp = f2fma(c6, bd, f2fma(chalf, gd, s2d));              // gamma

        u64 ip0 = f2fma(KD.x, ap, s3d0);          // inner_{k0} duplicated
        u64 ip1 = f2fma(KD.y, ap, s3d1);          // inner_{k1} duplicated
        s3d0 = f2fma(KD.x, gp, s3d0);
        s3d1 = f2fma(KD.y, gp, s3d1);

        // s4[k][l] += dx_l * inner_k : 8 packed FMAs for 16 elements
        s4a[0] = f2fma(A.x,  ip0, s4a[0]);
        s4a[1] = f2fma(A.y,  ip0, s4a[1]);
        s4a[2] = f2fma(Bq.x, ip0, s4a[2]);
        s4a[3] = f2fma(Bq.y, ip0, s4a[3]);
        s4a[4] = f2fma(A.x,  ip1, s4a[4]);
        s4a[5] = f2fma(A.y,  ip1, s4a[5]);
        s4a[6] = f2fma(Bq.x, ip1, s4a[6]);
        s4a[7] = f2fma(Bq.y, ip1, s4a[7]);

        // s2 += dxj*(s1 + dxi/2); s1 += dxi   (packed, stays duplicated)
        s2d = f2fma(djd, f2fma(chalf, did, s1d), s2d);
        s1d = f2add(s1d, did);
    }

    // ---- Epilogue ----
    float* ob = out + (size_t)b * OUT_PER_B;

    if (tid == (i << 5))  ob[i] = lo32(s1d);               // j==0 && m==0
    if (m == 0)           ob[DSZ + i * DSZ + j] = lo32(s2d);

    const int kbase = i * 64 + j * 8 + 2 * m;              // flattened (i,j,k0)
    ob[72 + kbase]     = lo32(s3d0);
    ob[72 + kbase + 1] = lo32(s3d1);

    // s4: two contiguous 8-float rows (k0 then k1) = 8 u64 stores
    u64* s4o = reinterpret_cast<u64*>(ob + 584 + kbase * 8);
    #pragma unroll
    for (int z = 0; z < 8; z++) s4o[z] = s4a[z];
}

extern "C" void kernel_launch(void* const* d_in, const int* in_sizes, int n_in,
                              void* d_out, int out_size) {
    const float* path = (const float*)d_in[0];
    float* out = (float*)d_out;
    sig_kernel<<<128, BDIM>>>(path, out);
}

// round 4
// speedup vs baseline: 1.1631x; 1.0595x over previous
#include <cuda_runtime.h>
#include <cstdint>

// Truncated path signature (Chen), trunc=4, B=128, S=512, D=8.
// One CTA/batch, 512 threads = 4 TIME CHUNKS x 128 threads.
// Chunk thread owns (i, j, k-quad m): 4 s3 + 32 s4 elems, packed f32x2.
// Partial signatures combined via Chen's identity in shared memory.

#define BDIM 512
#define DSZ 8
#define TSTEPS 511
#define OUT_PER_B 4680   // 8 + 64 + 512 + 4096

typedef unsigned long long u64;

__device__ __forceinline__ u64 pack2(float x) {
    u64 r; uint32_t xi = __float_as_uint(x);
    asm("mov.b64 %0, {%1, %1};" : "=l"(r) : "r"(xi));
    return r;
}
__device__ __forceinline__ u64 f2mul(u64 a, u64 b) {
    u64 r; asm("mul.rn.f32x2 %0, %1, %2;" : "=l"(r) : "l"(a), "l"(b)); return r;
}
__device__ __forceinline__ u64 f2fma(u64 a, u64 b, u64 c) {
    u64 r; asm("fma.rn.f32x2 %0, %1, %2, %3;" : "=l"(r) : "l"(a), "l"(b), "l"(c)); return r;
}
__device__ __forceinline__ u64 f2add(u64 a, u64 b) {
    u64 r; asm("add.rn.f32x2 %0, %1, %2;" : "=l"(r) : "l"(a), "l"(b)); return r;
}
__device__ __forceinline__ float lo32(u64 a) { return __uint_as_float((uint32_t)a); }

struct Frag { float r4[8]; float r3, r2, r1; };

// Chen product C = A (x) B for thread (i,j,k) = tid; results in registers.
__device__ __forceinline__ void chen_comb(const float* __restrict__ A,
                                          const float* __restrict__ B,
                                          int tid, Frag& f) {
    const int ci = tid >> 6, cj = (tid >> 3) & 7, ck = tid & 7;
    const float a1 = A[ci];
    const float a2 = A[8 + ci * 8 + cj];
    const float a3 = A[72 + tid];

    const float4* B1p = reinterpret_cast<const float4*>(B);
    const float4* B2p = reinterpret_cast<const float4*>(B + 8 + ck * 8);
    const float4* B3p = reinterpret_cast<const float4*>(B + 72 + cj * 64 + ck * 8);
    const float4* A4p = reinterpret_cast<const float4*>(A + 584 + tid * 8);
    const float4* B4p = reinterpret_cast<const float4*>(B + 584 + tid * 8);

    float b1[8], b2[8], b3[8], a4[8], b4[8];
    *reinterpret_cast<float4*>(b1)     = B1p[0]; *reinterpret_cast<float4*>(b1 + 4) = B1p[1];
    *reinterpret_cast<float4*>(b2)     = B2p[0]; *reinterpret_cast<float4*>(b2 + 4) = B2p[1];
    *reinterpret_cast<float4*>(b3)     = B3p[0]; *reinterpret_cast<float4*>(b3 + 4) = B3p[1];
    *reinterpret_cast<float4*>(a4)     = A4p[0]; *reinterpret_cast<float4*>(a4 + 4) = A4p[1];
    *reinterpret_cast<float4*>(b4)     = B4p[0]; *reinterpret_cast<float4*>(b4 + 4) = B4p[1];

    #pragma unroll
    for (int l = 0; l < 8; ++l)
        f.r4[l] = a4[l] + b4[l] + a1 * b3[l] + a2 * b2[l] + a3 * b1[l];

    f.r3 = a3 + B[72 + tid] + a1 * B[8 + cj * 8 + ck] + a2 * B[ck];
    f.r2 = A[8 + tid] + B[8 + tid] + A[tid >> 3] * B[tid & 7];  // valid tid<64
    f.r1 = A[tid] + B[tid];                                      // valid tid<8
}

// Write a Frag into a signature buffer (shared or global), standard layout.
__device__ __forceinline__ void write_frag(float* __restrict__ S, int tid, const Frag& f) {
    float4* p = reinterpret_cast<float4*>(S + 584 + tid * 8);
    p[0] = make_float4(f.r4[0], f.r4[1], f.r4[2], f.r4[3]);
    p[1] = make_float4(f.r4[4], f.r4[5], f.r4[6], f.r4[7]);
    S[72 + tid] = f.r3;
    if (tid < 64) S[8 + tid] = f.r2;
    if (tid < 8)  S[tid] = f.r1;
}

__global__ __launch_bounds__(BDIM, 1)
void sig_kernel(const float* __restrict__ path, float* __restrict__ out) {
    // 49,056 B: inc[4088] floats | dupv[4088] u64. Reused after the main loop
    // as two signature slots (4680 floats each @ offsets 0 and 18720 B).
    __shared__ __align__(16) unsigned char smem_raw[49056];
    float* inc  = reinterpret_cast<float*>(smem_raw);
    u64*   dupv = reinterpret_cast<u64*>(smem_raw + 16352);
    float* sigA = reinterpret_cast<float*>(smem_raw);
    float* sigB = reinterpret_cast<float*>(smem_raw + 18720);

    const int b   = blockIdx.x;
    const int tid = threadIdx.x;
    const float* prow = path + (size_t)b * (512 * DSZ);

    for (int e = tid; e < TSTEPS * DSZ; e += BDIM) {
        float v = prow[e + DSZ] - prow[e];
        inc[e]  = v;
        dupv[e] = pack2(v);
    }
    __syncthreads();

    const int h  = tid >> 7;          // time chunk 0..3
    const int t7 = tid & 127;
    const int i  = t7 >> 4;           // 0..7
    const int j  = (t7 >> 1) & 7;     // 0..7
    const int m  = t7 & 1;            // k-quad: k = 4m..4m+3

    u64 s1d = 0ull, s2d = 0ull;
    u64 s3d[4] = {0ull, 0ull, 0ull, 0ull};
    u64 s4a[16];
    #pragma unroll
    for (int z = 0; z < 16; ++z) s4a[z] = 0ull;

    const u64 chalf = pack2(0.5f);
    const u64 c6    = pack2(0.16666666666666667f);
    const u64 c24   = pack2(0.041666666666666667f);

    const int t0 = h << 7;
    const int t1 = (h == 3) ? TSTEPS : (t0 + 128);

    #pragma unroll 2
    for (int t = t0; t < t1; ++t) {
        const ulonglong2* incq = reinterpret_cast<const ulonglong2*>(inc + t * DSZ);
        ulonglong2 A  = incq[0];      // plain pairs (d0,d1),(d2,d3)
        ulonglong2 Bq = incq[1];      // (d4,d5),(d6,d7)
        const ulonglong2* kq = reinterpret_cast<const ulonglong2*>(dupv + t * DSZ + 4 * m);
        ulonglong2 K0 = kq[0];        // dup pairs for k=4m,4m+1
        ulonglong2 K1 = kq[1];        // k=4m+2,4m+3
        u64 did = dupv[t * DSZ + i];
        u64 djd = dupv[t * DSZ + j];

        u64 bd = f2mul(did, djd);
        u64 gd = f2mul(djd, s1d);
        u64 ap = f2fma(chalf, s2d, f2fma(c6, gd, f2mul(c24, bd)));  // alpha
        u64 gp = f2fma(c6, bd, f2fma(chalf, gd, s2d));              // gamma

        u64 Ks0 = K0.x, Ks1 = K0.y, Ks2 = K1.x, Ks3 = K1.y;
        u64 ip;
        ip = f2fma(Ks0, ap, s3d[0]); s3d[0] = f2fma(Ks0, gp, s3d[0]);
        s4a[0]  = f2fma(A.x,  ip, s4a[0]);  s4a[1]  = f2fma(A.y,  ip, s4a[1]);
        s4a[2]  = f2fma(Bq.x, ip, s4a[2]);  s4a[3]  = f2fma(Bq.y, ip, s4a[3]);
        ip = f2fma(Ks1, ap, s3d[1]); s3d[1] = f2fma(Ks1, gp, s3d[1]);
        s4a[4]  = f2fma(A.x,  ip, s4a[4]);  s4a[5]  = f2fma(A.y,  ip, s4a[5]);
        s4a[6]  = f2fma(Bq.x, ip, s4a[6]);  s4a[7]  = f2fma(Bq.y, ip, s4a[7]);
        ip = f2fma(Ks2, ap, s3d[2]); s3d[2] = f2fma(Ks2, gp, s3d[2]);
        s4a[8]  = f2fma(A.x,  ip, s4a[8]);  s4a[9]  = f2fma(A.y,  ip, s4a[9]);
        s4a[10] = f2fma(Bq.x, ip, s4a[10]); s4a[11] = f2fma(Bq.y, ip, s4a[11]);
        ip = f2fma(Ks3, ap, s3d[3]); s3d[3] = f2fma(Ks3, gp, s3d[3]);
        s4a[12] = f2fma(A.x,  ip, s4a[12]); s4a[13] = f2fma(A.y,  ip, s4a[13]);
        s4a[14] = f2fma(Bq.x, ip, s4a[14]); s4a[15] = f2fma(Bq.y, ip, s4a[15]);

        s2d = f2fma(djd, f2fma(chalf, did, s1d), s2d);
        s1d = f2add(s1d, did);
    }
    __syncthreads();   // main tables dead; slots reusable

    // ---- stage this chunk's partial signature ----
    const int kbase = i * 64 + j * 8 + 4 * m;
    float* mySlot = (h & 1) ? sigB : sigA;

    // Stage chunks 0 (->A) and 1 (->B)
    if (h < 2) {
        if ((t7 & 15) == 0) mySlot[i] = lo32(s1d);
        if (m == 0)         mySlot[8 + i * 8 + j] = lo32(s2d);
        #pragma unroll
        for (int kk = 0; kk < 4; ++kk) mySlot[72 + kbase + kk] = lo32(s3d[kk]);
        u64* p = reinterpret_cast<u64*>(mySlot + 584 + kbase * 8);
        #pragma unroll
        for (int z = 0; z < 16; ++z) p[z] = s4a[z];
    }
    __syncthreads();

    Frag fAB; chen_comb(sigA, sigB, tid, fAB);
    __syncthreads();   // all reads of A,B done before overwrite

    // Stage chunks 2 (->A) and 3 (->B)
    if (h >= 2) {
        if ((t7 & 15) == 0) mySlot[i] = lo32(s1d);
        if (m == 0)         mySlot[8 + i * 8 + j] = lo32(s2d);
        #pragma unroll
        for (int kk = 0; kk < 4; ++kk) mySlot[72 + kbase + kk] = lo32(s3d[kk]);
        u64* p = reinterpret_cast<u64*>(mySlot + 584 + kbase * 8);
        #pragma unroll
        for (int z = 0; z < 16; ++z) p[z] = s4a[z];
    }
    __syncthreads();

    Frag fCD; chen_comb(sigA, sigB, tid, fCD);
    __syncthreads();   // all reads done before overwrite

    write_frag(sigA, tid, fAB);
    write_frag(sigB, tid, fCD);
    __syncthreads();

    Frag fF; chen_comb(sigA, sigB, tid, fF);
    write_frag(out + (size_t)b * OUT_PER_B, tid, fF);
}

extern "C" void kernel_launch(void* const* d_in, const int* in_sizes, int n_in,
                              void* d_out, int out_size) {
    const float* path = (const float*)d_in[0];
    float* out = (float*)d_out;
    sig_kernel<<<128, BDIM>>>(path, out);
}